// round 6
// baseline (speedup 1.0000x reference)
#include <cuda_runtime.h>
#include <cuda_fp16.h>

// FastPooling "social": H[j][cc][:] = hidden[j] @ W[:,cc,:]  (fp16 tensor-core
// GEMM, fp32 accum, fp16 store); out[i] = relu(b + sum over winning fine cells
// of H[winner][coarse]). winner = max-j (last-write-wins); out-of-range peds
// write zeros to cell 0 -> in_range bit suppresses cell 0.

#define N_MAX   512
#define HID     128
#define GRID_S  32
#define NCELLS  (GRID_S * GRID_S)   // 1024
#define CC_N    16
#define OUTD    128

#define BM      32                   // K1 row tile
#define SA_LD   136                  // padded half leading dim (272B, 16B mult)

__device__ __half g_Hh[N_MAX * CC_N * OUTD];   // 2 MB scratch (fp16)

__device__ __forceinline__ unsigned su32(const void* p) {
    return (unsigned)__cvta_generic_to_shared(p);
}
__device__ __forceinline__ void ldsm_x4(unsigned r[4], unsigned addr) {
    asm volatile("ldmatrix.sync.aligned.m8n8.x4.shared.b16 {%0,%1,%2,%3}, [%4];"
                 : "=r"(r[0]), "=r"(r[1]), "=r"(r[2]), "=r"(r[3]) : "r"(addr));
}
__device__ __forceinline__ void ldsm_x4_t(unsigned r[4], unsigned addr) {
    asm volatile("ldmatrix.sync.aligned.m8n8.x4.trans.shared.b16 {%0,%1,%2,%3}, [%4];"
                 : "=r"(r[0]), "=r"(r[1]), "=r"(r[2]), "=r"(r[3]) : "r"(addr));
}
__device__ __forceinline__ void mma16816(float d[4], const unsigned a[4],
                                         const unsigned b0, const unsigned b1) {
    asm volatile("mma.sync.aligned.m16n8k16.row.col.f32.f16.f16.f32 "
                 "{%0,%1,%2,%3}, {%4,%5,%6,%7}, {%8,%9}, {%0,%1,%2,%3};"
                 : "+f"(d[0]), "+f"(d[1]), "+f"(d[2]), "+f"(d[3])
                 : "r"(a[0]), "r"(a[1]), "r"(a[2]), "r"(a[3]), "r"(b0), "r"(b1));
}
__device__ __forceinline__ unsigned h2u(__half2 h) {
    return *reinterpret_cast<unsigned*>(&h);
}

// ---------------------------------------------------------------------------
// K1: H = hidden (n x 128) @ Wperm via HMMA. Block tile 32 rows x 128 cols
// (one cc), K=128 staged fully in smem as fp16. 8 warps, warp tile 32x16.
// Grid (n/32, 16) = 256 blocks.
// ---------------------------------------------------------------------------
__global__ __launch_bounds__(256) void gemm1_mma_kernel(
    const float* __restrict__ hidden,
    const float* __restrict__ W,
    int n)
{
    __shared__ __align__(16) __half sA[BM][SA_LD];    // ~8.5 KB
    __shared__ __align__(16) __half sB[HID][SA_LD];   // ~34 KB  (k x n tile)

    const int cc    = blockIdx.y;
    const int jbase = blockIdx.x * BM;
    const int t     = threadIdx.x;

    // --- stage A (32 x 128 f32 -> fp16), 8 threads per row, 16 floats each
    {
        const int row = t >> 3, seg = t & 7;
        float4 f0, f1, f2, f3;
        if (jbase + row < n) {
            const float4* src = reinterpret_cast<const float4*>(
                hidden + (size_t)(jbase + row) * HID + seg * 16);
            f0 = src[0]; f1 = src[1]; f2 = src[2]; f3 = src[3];
        } else {
            f0 = f1 = f2 = f3 = make_float4(0.f, 0.f, 0.f, 0.f);
        }
        uint4 u0, u1;
        u0.x = h2u(__floats2half2_rn(f0.x, f0.y)); u0.y = h2u(__floats2half2_rn(f0.z, f0.w));
        u0.z = h2u(__floats2half2_rn(f1.x, f1.y)); u0.w = h2u(__floats2half2_rn(f1.z, f1.w));
        u1.x = h2u(__floats2half2_rn(f2.x, f2.y)); u1.y = h2u(__floats2half2_rn(f2.z, f2.w));
        u1.z = h2u(__floats2half2_rn(f3.x, f3.y)); u1.w = h2u(__floats2half2_rn(f3.z, f3.w));
        *reinterpret_cast<uint4*>(&sA[row][seg * 16])     = u0;
        *reinterpret_cast<uint4*>(&sA[row][seg * 16 + 8]) = u1;
    }

    // --- stage B (128k x 128n f32 -> fp16): 2 threads per k-row, 64 floats each
    {
        const int kr = t >> 1, ch = (t & 1) * 64;
        const float4* wsrc = reinterpret_cast<const float4*>(
            W + ((size_t)(kr * CC_N + cc)) * OUTD + ch);
        #pragma unroll
        for (int q = 0; q < 8; ++q) {
            const float4 fa = wsrc[2 * q];
            const float4 fb = wsrc[2 * q + 1];
            uint4 u;
            u.x = h2u(__floats2half2_rn(fa.x, fa.y));
            u.y = h2u(__floats2half2_rn(fa.z, fa.w));
            u.z = h2u(__floats2half2_rn(fb.x, fb.y));
            u.w = h2u(__floats2half2_rn(fb.z, fb.w));
            *reinterpret_cast<uint4*>(&sB[kr][ch + q * 8]) = u;
        }
    }
    __syncthreads();

    // --- mainloop: warp w covers output cols [w*16, w*16+16)
    const int wid  = t >> 5;
    const int lane = t & 31;
    const int wc   = wid * 16;

    float d[2][2][4];
    #pragma unroll
    for (int mt = 0; mt < 2; ++mt)
        #pragma unroll
        for (int nt = 0; nt < 2; ++nt)
            #pragma unroll
            for (int q = 0; q < 4; ++q) d[mt][nt][q] = 0.f;

    const unsigned aBase = su32(&sA[0][0]);
    const unsigned bBase = su32(&sB[0][0]);
    const int arow = lane & 15;
    const int aseg = (lane >> 4) * 8;

    #pragma unroll
    for (int ks = 0; ks < 8; ++ks) {
        unsigned a0[4], a1[4], b[4];
        // A m-tiles: rows 0-15 and 16-31, k cols ks*16 + {0,8}
        ldsm_x4(a0, aBase + ((arow)      * SA_LD + ks * 16 + aseg) * 2);
        ldsm_x4(a1, aBase + ((16 + arow) * SA_LD + ks * 16 + aseg) * 2);
        // B: k rows ks*16 + lane%16, n cols wc + {0,8}  (transposed load)
        ldsm_x4_t(b, bBase + ((ks * 16 + arow) * SA_LD + wc + aseg) * 2);
        mma16816(d[0][0], a0, b[0], b[1]);
        mma16816(d[0][1], a0, b[2], b[3]);
        mma16816(d[1][0], a1, b[0], b[1]);
        mma16816(d[1][1], a1, b[2], b[3]);
    }

    // --- epilogue: fp32 frags -> fp16 -> g_Hh
    #pragma unroll
    for (int mt = 0; mt < 2; ++mt) {
        #pragma unroll
        for (int nt = 0; nt < 2; ++nt) {
            const int jg  = jbase + mt * 16 + (lane >> 2);
            const int col = wc + nt * 8 + (lane & 3) * 2;
            const unsigned lo = h2u(__floats2half2_rn(d[mt][nt][0], d[mt][nt][1]));
            const unsigned hi = h2u(__floats2half2_rn(d[mt][nt][2], d[mt][nt][3]));
            if (jg < n)
                *reinterpret_cast<unsigned*>(g_Hh + ((size_t)jg * CC_N + cc) * OUTD + col) = lo;
            if (jg + 8 < n)
                *reinterpret_cast<unsigned*>(g_Hh + ((size_t)(jg + 8) * CC_N + cc) * OUTD + col) = hi;
        }
    }
}

// ---------------------------------------------------------------------------
// K2: per ped i — obs2 in smem, winner scatter (shared atomicMax), compact,
// then 8-way unrolled branch-free gather-sum of fp16 H rows.
// ---------------------------------------------------------------------------
__global__ __launch_bounds__(256) void pool_gather_kernel(
    const float* __restrict__ obs2,
    const float* __restrict__ bias,
    float* __restrict__ out,
    int n)
{
    __shared__ __align__(16) float red[8][OUTD];
    __shared__ __align__(16) float2 sobs[N_MAX];
    __shared__ int   win[NCELLS];
    __shared__ int   lst[NCELLS];
    __shared__ int   cnt;

    const int i    = blockIdx.x;
    const int t    = threadIdx.x;
    const int w    = t >> 5;
    const int lane = t & 31;

    if (t == 0) cnt = 0;
    for (int idx = t; idx < n; idx += 256)
        sobs[idx] = reinterpret_cast<const float2*>(obs2)[idx];
    for (int c = t; c < NCELLS; c += 256) win[c] = -1;
    __syncthreads();

    const float xi = sobs[i].x;
    const float yi = sobs[i].y;

    for (int j = t; j < n; j += 256) {
        if (j == i) continue;
        const float ox = (sobs[j].x - xi) * 4.0f + 16.0f;
        const float oy = (sobs[j].y - yi) * 4.0f + 16.0f;
        const bool inr = (ox >= 0.f) & (ox < 32.f) & (oy >= 0.f) & (oy < 32.f);
        int cell = 0;
        if (inr) cell = ((int)ox) * GRID_S + (int)oy;
        atomicMax(&win[cell], (j << 1) | (inr ? 1 : 0));
    }
    __syncthreads();

    #pragma unroll
    for (int base_c = 0; base_c < NCELLS; base_c += 256) {
        const int c   = base_c + t;
        const int enc = win[c];
        const bool valid = (enc >= 0) && (enc & 1);
        const unsigned mask = __ballot_sync(0xffffffffu, valid);
        if (mask) {
            const int leader = __ffs(mask) - 1;
            int base = 0;
            if (lane == leader) base = atomicAdd(&cnt, __popc(mask));
            base = __shfl_sync(0xffffffffu, base, leader);
            if (valid) {
                const int j  = enc >> 1;
                const int cc = (c >> 8) * 4 + ((c >> 3) & 3);
                lst[base + __popc(mask & ((1u << lane) - 1u))] = j * CC_N + cc;
            }
        }
    }
    __syncthreads();
    const int m = cnt;

    float4 acc0 = make_float4(0.f, 0.f, 0.f, 0.f);
    float4 acc1 = make_float4(0.f, 0.f, 0.f, 0.f);
    const int co = lane * 4;

    #define ACCUM(A, u) do {                                              \
        const __half2 _h0 = *reinterpret_cast<const __half2*>(&(u).x);    \
        const __half2 _h1 = *reinterpret_cast<const __half2*>(&(u).y);    \
        const float2 _f0 = __half22float2(_h0);                           \
        const float2 _f1 = __half22float2(_h1);                           \
        A.x += _f0.x; A.y += _f0.y; A.z += _f1.x; A.w += _f1.y;           \
    } while (0)

    int e = w;
    for (; e + 56 < m; e += 64) {
        const int p0 = lst[e];      const int p1 = lst[e + 8];
        const int p2 = lst[e + 16]; const int p3 = lst[e + 24];
        const int p4 = lst[e + 32]; const int p5 = lst[e + 40];
        const int p6 = lst[e + 48]; const int p7 = lst[e + 56];
        const uint2 v0 = *reinterpret_cast<const uint2*>(g_Hh + (size_t)p0 * OUTD + co);
        const uint2 v1 = *reinterpret_cast<const uint2*>(g_Hh + (size_t)p1 * OUTD + co);
        const uint2 v2 = *reinterpret_cast<const uint2*>(g_Hh + (size_t)p2 * OUTD + co);
        const uint2 v3 = *reinterpret_cast<const uint2*>(g_Hh + (size_t)p3 * OUTD + co);
        const uint2 v4 = *reinterpret_cast<const uint2*>(g_Hh + (size_t)p4 * OUTD + co);
        const uint2 v5 = *reinterpret_cast<const uint2*>(g_Hh + (size_t)p5 * OUTD + co);
        const uint2 v6 = *reinterpret_cast<const uint2*>(g_Hh + (size_t)p6 * OUTD + co);
        const uint2 v7 = *reinterpret_cast<const uint2*>(g_Hh + (size_t)p7 * OUTD + co);
        ACCUM(acc0, v0); ACCUM(acc1, v1); ACCUM(acc0, v2); ACCUM(acc1, v3);
        ACCUM(acc0, v4); ACCUM(acc1, v5); ACCUM(acc0, v6); ACCUM(acc1, v7);
    }
    for (; e + 24 < m; e += 32) {
        const int p0 = lst[e];      const int p1 = lst[e + 8];
        const int p2 = lst[e + 16]; const int p3 = lst[e + 24];
        const uint2 v0 = *reinterpret_cast<const uint2*>(g_Hh + (size_t)p0 * OUTD + co);
        const uint2 v1 = *reinterpret_cast<const uint2*>(g_Hh + (size_t)p1 * OUTD + co);
        const uint2 v2 = *reinterpret_cast<const uint2*>(g_Hh + (size_t)p2 * OUTD + co);
        const uint2 v3 = *reinterpret_cast<const uint2*>(g_Hh + (size_t)p3 * OUTD + co);
        ACCUM(acc0, v0); ACCUM(acc1, v1); ACCUM(acc0, v2); ACCUM(acc1, v3);
    }
    for (; e < m; e += 8) {
        const int p = lst[e];
        const uint2 v = *reinterpret_cast<const uint2*>(g_Hh + (size_t)p * OUTD + co);
        ACCUM(acc0, v);
    }
    #undef ACCUM
    acc0.x += acc1.x; acc0.y += acc1.y; acc0.z += acc1.z; acc0.w += acc1.w;

    *reinterpret_cast<float4*>(&red[w][co]) = acc0;
    __syncthreads();

    if (t < OUTD) {
        float s = bias[t];
        #pragma unroll
        for (int r = 0; r < 8; ++r) s += red[r][t];
        out[(size_t)i * OUTD + t] = fmaxf(s, 0.f);
    }
}

// ---------------------------------------------------------------------------
// inputs: hidden_state (n,128) f32 | obs1 (n,2) (unused) | obs2 (n,2) f32 |
//         W (2048,128) f32 | b (128,) f32   -> out (n,128) f32
// ---------------------------------------------------------------------------
extern "C" void kernel_launch(void* const* d_in, const int* in_sizes, int n_in,
                              void* d_out, int out_size)
{
    const float* hidden = (const float*)d_in[0];
    const float* obs2   = (const float*)d_in[2];
    const float* W      = (const float*)d_in[3];
    const float* bias   = (const float*)d_in[4];
    float*       out    = (float*)d_out;

    const int n = in_sizes[2] / 2;   // 512

    dim3 g1((n + BM - 1) / BM, CC_N);
    gemm1_mma_kernel<<<g1, 256>>>(hidden, W, n);
    pool_gather_kernel<<<n, 256>>>(obs2, bias, out, n);
}

// round 7
// speedup vs baseline: 1.2220x; 1.2220x over previous
#include <cuda_runtime.h>
#include <cuda_fp16.h>

// FastPooling "social", 3-phase:
//  K0: fp32->fp16 conversion of hidden + W (permuted [cc][k][o]) AND per-ped
//      winner scatter/compaction (independent of H) -> g_lst/g_cnt.
//  K1: H[j][cc][:] = hidden[j] @ W[:,cc,:] via HMMA m16n8k16 (fp16 in, fp32
//      acc, fp16 out to g_Hh).
//  K2: out[i] = relu(b + sum over compacted winners of H rows).  winner =
//      max-j (last-write-wins); out-of-range peds write zeros to cell 0 ->
//      in_range bit suppresses cell 0.

#define N_MAX   512
#define HID     128
#define GRID_S  32
#define NCELLS  (GRID_S * GRID_S)   // 1024
#define CC_N    16
#define OUTD    128
#define BM      64
#define SA_LD   136                  // padded half ld (272B)

__device__ __half g_Ah[N_MAX * HID];                 // 128 KB fp16 hidden
__device__ __half g_Wh[CC_N * HID * OUTD];           // 512 KB fp16 W, [cc][k][o]
__device__ __half g_Hh[N_MAX * CC_N * OUTD];         // 2 MB fp16 H
__device__ int    g_lst[N_MAX * NCELLS];             // compacted winners
__device__ int    g_cnt[N_MAX];

__device__ __forceinline__ unsigned su32(const void* p) {
    return (unsigned)__cvta_generic_to_shared(p);
}
__device__ __forceinline__ void ldsm_x4(unsigned r[4], unsigned addr) {
    asm volatile("ldmatrix.sync.aligned.m8n8.x4.shared.b16 {%0,%1,%2,%3}, [%4];"
                 : "=r"(r[0]), "=r"(r[1]), "=r"(r[2]), "=r"(r[3]) : "r"(addr));
}
__device__ __forceinline__ void ldsm_x4_t(unsigned r[4], unsigned addr) {
    asm volatile("ldmatrix.sync.aligned.m8n8.x4.trans.shared.b16 {%0,%1,%2,%3}, [%4];"
                 : "=r"(r[0]), "=r"(r[1]), "=r"(r[2]), "=r"(r[3]) : "r"(addr));
}
__device__ __forceinline__ void mma16816(float d[4], const unsigned a[4],
                                         const unsigned b0, const unsigned b1) {
    asm volatile("mma.sync.aligned.m16n8k16.row.col.f32.f16.f16.f32 "
                 "{%0,%1,%2,%3}, {%4,%5,%6,%7}, {%8,%9}, {%0,%1,%2,%3};"
                 : "+f"(d[0]), "+f"(d[1]), "+f"(d[2]), "+f"(d[3])
                 : "r"(a[0]), "r"(a[1]), "r"(a[2]), "r"(a[3]), "r"(b0), "r"(b1));
}
__device__ __forceinline__ unsigned h2u(__half2 h) {
    return *reinterpret_cast<unsigned*>(&h);
}
__device__ __forceinline__ unsigned cvt2(float a, float b) {
    return h2u(__floats2half2_rn(a, b));
}

// ---------------------------------------------------------------------------
// K0: blocks [0,64): hidden->fp16 | [64,320): W->fp16 permuted | [320,320+n):
// scatter+compaction for ped i = b-320.
// ---------------------------------------------------------------------------
__global__ __launch_bounds__(256) void prep_scatter_kernel(
    const float* __restrict__ hidden,
    const float* __restrict__ W,
    const float* __restrict__ obs2,
    int n)
{
    const int b = blockIdx.x;
    const int t = threadIdx.x;

    if (b < 64) {                                  // hidden conversion
        const int idx = (b * 256 + t) * 4;
        if (idx < n * HID) {
            const float4 f = *reinterpret_cast<const float4*>(hidden + idx);
            uint2 u; u.x = cvt2(f.x, f.y); u.y = cvt2(f.z, f.w);
            *reinterpret_cast<uint2*>(g_Ah + idx) = u;
        }
        return;
    }
    if (b < 320) {                                 // W conversion + permute
        const int gi = ((b - 64) * 256 + t) * 4;   // 0..262143
        const int r  = gi >> 7;                    // row in W (2048)
        const int o  = gi & 127;
        const int k  = r >> 4, cc = r & 15;
        const float4 f = *reinterpret_cast<const float4*>(W + gi);
        uint2 u; u.x = cvt2(f.x, f.y); u.y = cvt2(f.z, f.w);
        *reinterpret_cast<uint2*>(g_Wh + (((cc << 7) + k) << 7) + o) = u;
        return;
    }

    // ---- scatter for ped i
    const int i = b - 320;
    if (i >= n) return;

    __shared__ int    win[NCELLS];
    __shared__ float2 sobs[N_MAX];
    __shared__ int    lst[NCELLS];
    __shared__ int    cnt;

    const int w    = t >> 5;
    const int lane = t & 31;
    (void)w;

    if (t == 0) cnt = 0;
    for (int idx = t; idx < n; idx += 256)
        sobs[idx] = reinterpret_cast<const float2*>(obs2)[idx];
    for (int c = t; c < NCELLS; c += 256) win[c] = -1;
    __syncthreads();

    const float xi = sobs[i].x;
    const float yi = sobs[i].y;

    for (int j = t; j < n; j += 256) {
        if (j == i) continue;
        const float ox = (sobs[j].x - xi) * 4.0f + 16.0f;
        const float oy = (sobs[j].y - yi) * 4.0f + 16.0f;
        const bool inr = (ox >= 0.f) & (ox < 32.f) & (oy >= 0.f) & (oy < 32.f);
        int cell = 0;
        if (inr) cell = ((int)ox) * GRID_S + (int)oy;
        atomicMax(&win[cell], (j << 1) | (inr ? 1 : 0));
    }
    __syncthreads();

    #pragma unroll
    for (int base_c = 0; base_c < NCELLS; base_c += 256) {
        const int c   = base_c + t;
        const int enc = win[c];
        const bool valid = (enc >= 0) && (enc & 1);
        const unsigned mask = __ballot_sync(0xffffffffu, valid);
        if (mask) {
            const int leader = __ffs(mask) - 1;
            int base = 0;
            if (lane == leader) base = atomicAdd(&cnt, __popc(mask));
            base = __shfl_sync(0xffffffffu, base, leader);
            if (valid) {
                const int j  = enc >> 1;
                const int cc = (c >> 8) * 4 + ((c >> 3) & 3);
                lst[base + __popc(mask & ((1u << lane) - 1u))] = j * CC_N + cc;
            }
        }
    }
    __syncthreads();

    const int m = cnt;
    if (t == 0) g_cnt[i] = m;
    for (int idx = t; idx < m; idx += 256) g_lst[i * NCELLS + idx] = lst[idx];
}

// ---------------------------------------------------------------------------
// K1: HMMA GEMM, block = 64 rows x 128 cols (one cc). Grid (n/64, 16) = 128.
// ---------------------------------------------------------------------------
__global__ __launch_bounds__(256) void gemm1_mma_kernel(int n)
{
    __shared__ __align__(16) __half sA[BM][SA_LD];    // 17 KB
    __shared__ __align__(16) __half sB[HID][SA_LD];   // 34 KB

    const int cc    = blockIdx.y;
    const int jbase = blockIdx.x * BM;
    const int t     = threadIdx.x;

    // stage A: 1024 uint4, 4/thread
    #pragma unroll
    for (int s = 0; s < 4; ++s) {
        const int idx  = t + 256 * s;
        const int row  = idx >> 4;
        const int cseg = (idx & 15) * 8;
        uint4 u = make_uint4(0u, 0u, 0u, 0u);
        if (jbase + row < n)
            u = *reinterpret_cast<const uint4*>(g_Ah + (size_t)(jbase + row) * HID + cseg);
        *reinterpret_cast<uint4*>(&sA[row][cseg]) = u;
    }
    // stage B: 2048 uint4, 8/thread (contiguous rows of g_Wh[cc])
    #pragma unroll
    for (int s = 0; s < 8; ++s) {
        const int idx  = t + 256 * s;
        const int row  = idx >> 4;
        const int cseg = (idx & 15) * 8;
        const uint4 u = *reinterpret_cast<const uint4*>(
            g_Wh + (((size_t)(cc << 7) + row) << 7) + cseg);
        *reinterpret_cast<uint4*>(&sB[row][cseg]) = u;
    }
    __syncthreads();

    const int wid  = t >> 5;
    const int lane = t & 31;
    const int wc   = wid * 16;
    const int arow = lane & 15;
    const int aseg = (lane >> 4) * 8;

    float d[4][2][4];
    #pragma unroll
    for (int mt = 0; mt < 4; ++mt)
        #pragma unroll
        for (int nt = 0; nt < 2; ++nt)
            #pragma unroll
            for (int q = 0; q < 4; ++q) d[mt][nt][q] = 0.f;

    const unsigned aBase = su32(&sA[0][0]);
    const unsigned bBase = su32(&sB[0][0]);

    #pragma unroll
    for (int ks = 0; ks < 8; ++ks) {
        unsigned bfr[4];
        ldsm_x4_t(bfr, bBase + ((ks * 16 + arow) * SA_LD + wc + aseg) * 2);
        #pragma unroll
        for (int mt = 0; mt < 4; ++mt) {
            unsigned a[4];
            ldsm_x4(a, aBase + ((mt * 16 + arow) * SA_LD + ks * 16 + aseg) * 2);
            mma16816(d[mt][0], a, bfr[0], bfr[1]);
            mma16816(d[mt][1], a, bfr[2], bfr[3]);
        }
    }

    #pragma unroll
    for (int mt = 0; mt < 4; ++mt) {
        #pragma unroll
        for (int nt = 0; nt < 2; ++nt) {
            const int jg  = jbase + mt * 16 + (lane >> 2);
            const int col = wc + nt * 8 + (lane & 3) * 2;
            const unsigned lo = cvt2(d[mt][nt][0], d[mt][nt][1]);
            const unsigned hi = cvt2(d[mt][nt][2], d[mt][nt][3]);
            if (jg < n)
                *reinterpret_cast<unsigned*>(g_Hh + ((size_t)jg * CC_N + cc) * OUTD + col) = lo;
            if (jg + 8 < n)
                *reinterpret_cast<unsigned*>(g_Hh + ((size_t)(jg + 8) * CC_N + cc) * OUTD + col) = hi;
        }
    }
}

// ---------------------------------------------------------------------------
// K2: pure gather. 128 threads (4 warps), list staged in smem, 8-deep MLP.
// ---------------------------------------------------------------------------
__global__ __launch_bounds__(128) void gather_kernel(
    const float* __restrict__ bias,
    float* __restrict__ out,
    int n)
{
    __shared__ __align__(16) float red[4][OUTD];
    __shared__ int lst[NCELLS];

    const int i    = blockIdx.x;
    const int t    = threadIdx.x;
    const int w    = t >> 5;
    const int lane = t & 31;

    const int m = g_cnt[i];
    for (int idx = t; idx < m; idx += 128) lst[idx] = g_lst[i * NCELLS + idx];
    __syncthreads();

    float4 acc0 = make_float4(0.f, 0.f, 0.f, 0.f);
    float4 acc1 = make_float4(0.f, 0.f, 0.f, 0.f);
    const int co = lane * 4;

    #define ACCUM(A, u) do {                                              \
        const __half2 _h0 = *reinterpret_cast<const __half2*>(&(u).x);    \
        const __half2 _h1 = *reinterpret_cast<const __half2*>(&(u).y);    \
        const float2 _f0 = __half22float2(_h0);                           \
        const float2 _f1 = __half22float2(_h1);                           \
        A.x += _f0.x; A.y += _f0.y; A.z += _f1.x; A.w += _f1.y;           \
    } while (0)

    int e = w;
    for (; e + 28 < m; e += 32) {      // 8 uint2 LDGs in flight per warp
        const int p0 = lst[e];      const int p1 = lst[e + 4];
        const int p2 = lst[e + 8];  const int p3 = lst[e + 12];
        const int p4 = lst[e + 16]; const int p5 = lst[e + 20];
        const int p6 = lst[e + 24]; const int p7 = lst[e + 28];
        const uint2 v0 = *reinterpret_cast<const uint2*>(g_Hh + (size_t)p0 * OUTD + co);
        const uint2 v1 = *reinterpret_cast<const uint2*>(g_Hh + (size_t)p1 * OUTD + co);
        const uint2 v2 = *reinterpret_cast<const uint2*>(g_Hh + (size_t)p2 * OUTD + co);
        const uint2 v3 = *reinterpret_cast<const uint2*>(g_Hh + (size_t)p3 * OUTD + co);
        const uint2 v4 = *reinterpret_cast<const uint2*>(g_Hh + (size_t)p4 * OUTD + co);
        const uint2 v5 = *reinterpret_cast<const uint2*>(g_Hh + (size_t)p5 * OUTD + co);
        const uint2 v6 = *reinterpret_cast<const uint2*>(g_Hh + (size_t)p6 * OUTD + co);
        const uint2 v7 = *reinterpret_cast<const uint2*>(g_Hh + (size_t)p7 * OUTD + co);
        ACCUM(acc0, v0); ACCUM(acc1, v1); ACCUM(acc0, v2); ACCUM(acc1, v3);
        ACCUM(acc0, v4); ACCUM(acc1, v5); ACCUM(acc0, v6); ACCUM(acc1, v7);
    }
    for (; e < m; e += 4) {
        const int p = lst[e];
        const uint2 v = *reinterpret_cast<const uint2*>(g_Hh + (size_t)p * OUTD + co);
        ACCUM(acc0, v);
    }
    #undef ACCUM
    acc0.x += acc1.x; acc0.y += acc1.y; acc0.z += acc1.z; acc0.w += acc1.w;

    *reinterpret_cast<float4*>(&red[w][co]) = acc0;
    __syncthreads();

    if (t < OUTD) {
        float s = bias[t];
        #pragma unroll
        for (int r = 0; r < 4; ++r) s += red[r][t];
        out[(size_t)i * OUTD + t] = fmaxf(s, 0.f);
    }
}

// ---------------------------------------------------------------------------
// inputs: hidden_state (n,128) f32 | obs1 (n,2) (unused) | obs2 (n,2) f32 |
//         W (2048,128) f32 | b (128,) f32   -> out (n,128) f32
// ---------------------------------------------------------------------------
extern "C" void kernel_launch(void* const* d_in, const int* in_sizes, int n_in,
                              void* d_out, int out_size)
{
    const float* hidden = (const float*)d_in[0];
    const float* obs2   = (const float*)d_in[2];
    const float* W      = (const float*)d_in[3];
    const float* bias   = (const float*)d_in[4];
    float*       out    = (float*)d_out;

    const int n = in_sizes[2] / 2;   // 512

    prep_scatter_kernel<<<320 + n, 256>>>(hidden, W, obs2, n);
    dim3 g1((n + BM - 1) / BM, CC_N);
    gemm1_mma_kernel<<<g1, 256>>>(n);
    gather_kernel<<<n, 128>>>(bias, out, n);
}

// round 8
// speedup vs baseline: 1.2405x; 1.0152x over previous
#include <cuda_runtime.h>
#include <cuda_fp16.h>

// FastPooling "social", 3-phase:
//  K0: fp32->fp16 conversion of hidden (g_Ah) and W permuted [cc][k][o] (g_Wh).
//  K1: H[j][cc][:] = hidden[j] @ W[:,cc,:] via HMMA m16n8k16 -> g_Hh (fp16).
//  K2 (fused): per ped i - winner scatter (shared atomicMax, last-write-wins
//      == max-j; out-of-range peds write zeros to cell 0 -> in_range bit
//      suppresses), in-smem compaction, branch-free MLP-8 gather of H rows,
//      bias + relu.

#define N_MAX   512
#define HID     128
#define GRID_S  32
#define NCELLS  (GRID_S * GRID_S)   // 1024
#define CC_N    16
#define OUTD    128
#define BM      64
#define SA_LD   136                  // padded half ld (272B)

__device__ __half g_Ah[N_MAX * HID];                 // 128 KB fp16 hidden
__device__ __half g_Wh[CC_N * HID * OUTD];           // 512 KB fp16 W, [cc][k][o]
__device__ __half g_Hh[N_MAX * CC_N * OUTD];         // 2 MB fp16 H

__device__ __forceinline__ unsigned su32(const void* p) {
    return (unsigned)__cvta_generic_to_shared(p);
}
__device__ __forceinline__ void ldsm_x4(unsigned r[4], unsigned addr) {
    asm volatile("ldmatrix.sync.aligned.m8n8.x4.shared.b16 {%0,%1,%2,%3}, [%4];"
                 : "=r"(r[0]), "=r"(r[1]), "=r"(r[2]), "=r"(r[3]) : "r"(addr));
}
__device__ __forceinline__ void ldsm_x4_t(unsigned r[4], unsigned addr) {
    asm volatile("ldmatrix.sync.aligned.m8n8.x4.trans.shared.b16 {%0,%1,%2,%3}, [%4];"
                 : "=r"(r[0]), "=r"(r[1]), "=r"(r[2]), "=r"(r[3]) : "r"(addr));
}
__device__ __forceinline__ void mma16816(float d[4], const unsigned a[4],
                                         const unsigned b0, const unsigned b1) {
    asm volatile("mma.sync.aligned.m16n8k16.row.col.f32.f16.f16.f32 "
                 "{%0,%1,%2,%3}, {%4,%5,%6,%7}, {%8,%9}, {%0,%1,%2,%3};"
                 : "+f"(d[0]), "+f"(d[1]), "+f"(d[2]), "+f"(d[3])
                 : "r"(a[0]), "r"(a[1]), "r"(a[2]), "r"(a[3]), "r"(b0), "r"(b1));
}
__device__ __forceinline__ unsigned h2u(__half2 h) {
    return *reinterpret_cast<unsigned*>(&h);
}
__device__ __forceinline__ unsigned cvt2(float a, float b) {
    return h2u(__floats2half2_rn(a, b));
}

// ---------------------------------------------------------------------------
// K0: blocks [0,64): hidden->fp16 | [64,320): W->fp16 permuted.
// ---------------------------------------------------------------------------
__global__ __launch_bounds__(256) void convert_kernel(
    const float* __restrict__ hidden,
    const float* __restrict__ W,
    int n)
{
    const int b = blockIdx.x;
    const int t = threadIdx.x;

    if (b < 64) {
        const int idx = (b * 256 + t) * 4;
        if (idx < n * HID) {
            const float4 f = *reinterpret_cast<const float4*>(hidden + idx);
            uint2 u; u.x = cvt2(f.x, f.y); u.y = cvt2(f.z, f.w);
            *reinterpret_cast<uint2*>(g_Ah + idx) = u;
        }
    } else {
        const int gi = ((b - 64) * 256 + t) * 4;   // 0..262143
        const int r  = gi >> 7;                    // row in W (2048)
        const int o  = gi & 127;
        const int k  = r >> 4, cc = r & 15;
        const float4 f = *reinterpret_cast<const float4*>(W + gi);
        uint2 u; u.x = cvt2(f.x, f.y); u.y = cvt2(f.z, f.w);
        *reinterpret_cast<uint2*>(g_Wh + (((cc << 7) + k) << 7) + o) = u;
    }
}

// ---------------------------------------------------------------------------
// K1: HMMA GEMM, block = 64 rows x 128 cols (one cc). Grid (n/64, 16) = 128.
// ---------------------------------------------------------------------------
__global__ __launch_bounds__(256) void gemm1_mma_kernel(int n)
{
    __shared__ __align__(16) __half sA[BM][SA_LD];    // 17 KB
    __shared__ __align__(16) __half sB[HID][SA_LD];   // 34 KB

    const int cc    = blockIdx.y;
    const int jbase = blockIdx.x * BM;
    const int t     = threadIdx.x;

    #pragma unroll
    for (int s = 0; s < 4; ++s) {
        const int idx  = t + 256 * s;
        const int row  = idx >> 4;
        const int cseg = (idx & 15) * 8;
        uint4 u = make_uint4(0u, 0u, 0u, 0u);
        if (jbase + row < n)
            u = *reinterpret_cast<const uint4*>(g_Ah + (size_t)(jbase + row) * HID + cseg);
        *reinterpret_cast<uint4*>(&sA[row][cseg]) = u;
    }
    #pragma unroll
    for (int s = 0; s < 8; ++s) {
        const int idx  = t + 256 * s;
        const int row  = idx >> 4;
        const int cseg = (idx & 15) * 8;
        const uint4 u = *reinterpret_cast<const uint4*>(
            g_Wh + (((size_t)(cc << 7) + row) << 7) + cseg);
        *reinterpret_cast<uint4*>(&sB[row][cseg]) = u;
    }
    __syncthreads();

    const int wid  = t >> 5;
    const int lane = t & 31;
    const int wc   = wid * 16;
    const int arow = lane & 15;
    const int aseg = (lane >> 4) * 8;

    float d[4][2][4];
    #pragma unroll
    for (int mt = 0; mt < 4; ++mt)
        #pragma unroll
        for (int nt = 0; nt < 2; ++nt)
            #pragma unroll
            for (int q = 0; q < 4; ++q) d[mt][nt][q] = 0.f;

    const unsigned aBase = su32(&sA[0][0]);
    const unsigned bBase = su32(&sB[0][0]);

    #pragma unroll
    for (int ks = 0; ks < 8; ++ks) {
        unsigned bfr[4];
        ldsm_x4_t(bfr, bBase + ((ks * 16 + arow) * SA_LD + wc + aseg) * 2);
        #pragma unroll
        for (int mt = 0; mt < 4; ++mt) {
            unsigned a[4];
            ldsm_x4(a, aBase + ((mt * 16 + arow) * SA_LD + ks * 16 + aseg) * 2);
            mma16816(d[mt][0], a, bfr[0], bfr[1]);
            mma16816(d[mt][1], a, bfr[2], bfr[3]);
        }
    }

    #pragma unroll
    for (int mt = 0; mt < 4; ++mt) {
        #pragma unroll
        for (int nt = 0; nt < 2; ++nt) {
            const int jg  = jbase + mt * 16 + (lane >> 2);
            const int col = wc + nt * 8 + (lane & 3) * 2;
            const unsigned lo = cvt2(d[mt][nt][0], d[mt][nt][1]);
            const unsigned hi = cvt2(d[mt][nt][2], d[mt][nt][3]);
            if (jg < n)
                *reinterpret_cast<unsigned*>(g_Hh + ((size_t)jg * CC_N + cc) * OUTD + col) = lo;
            if (jg + 8 < n)
                *reinterpret_cast<unsigned*>(g_Hh + ((size_t)(jg + 8) * CC_N + cc) * OUTD + col) = hi;
        }
    }
}

// ---------------------------------------------------------------------------
// K2: fused scatter + compact + gather. 128 threads, ~10.5 KB smem.
// ---------------------------------------------------------------------------
__global__ __launch_bounds__(128) void scatter_gather_kernel(
    const float* __restrict__ obs2,
    const float* __restrict__ bias,
    float* __restrict__ out,
    int n)
{
    __shared__ __align__(16) float red[4][OUTD];   // 2 KB
    __shared__ int win[NCELLS];                    // 4 KB
    __shared__ int lst[NCELLS];                    // 4 KB
    __shared__ int cnt;

    const int i    = blockIdx.x;
    const int t    = threadIdx.x;
    const int w    = t >> 5;
    const int lane = t & 31;

    if (t == 0) cnt = 0;
    #pragma unroll
    for (int s = 0; s < 8; ++s) win[t + 128 * s] = -1;

    const float2* obs = reinterpret_cast<const float2*>(obs2);
    const float xi = obs[i].x;
    const float yi = obs[i].y;

    // batched j-loop loads (MLP 4), predicated atomicMax
    float2 o[4];
    #pragma unroll
    for (int s = 0; s < 4; ++s) {
        const int j = t + 128 * s;
        o[s] = (j < n) ? obs[j] : make_float2(1e9f, 1e9f);
    }
    __syncthreads();   // win[] init visible before scatter

    #pragma unroll
    for (int s = 0; s < 4; ++s) {
        const int j = t + 128 * s;
        const bool act = (j < n) & (j != i);
        const float ox = (o[s].x - xi) * 4.0f + 16.0f;
        const float oy = (o[s].y - yi) * 4.0f + 16.0f;
        const bool inr = (ox >= 0.f) & (ox < 32.f) & (oy >= 0.f) & (oy < 32.f);
        const int cell = inr ? (((int)ox) * GRID_S + (int)oy) : 0;
        if (act) atomicMax(&win[cell], (j << 1) | (inr ? 1 : 0));
    }
    __syncthreads();

    // compact valid in-range winners into lst (order irrelevant for the sum)
    #pragma unroll
    for (int base_c = 0; base_c < NCELLS; base_c += 128) {
        const int c   = base_c + t;
        const int enc = win[c];
        const bool valid = (enc >= 0) && (enc & 1);
        const unsigned mask = __ballot_sync(0xffffffffu, valid);
        if (mask) {
            const int leader = __ffs(mask) - 1;
            int base = 0;
            if (lane == leader) base = atomicAdd(&cnt, __popc(mask));
            base = __shfl_sync(0xffffffffu, base, leader);
            if (valid) {
                const int j  = enc >> 1;
                const int cc = (c >> 8) * 4 + ((c >> 3) & 3);
                lst[base + __popc(mask & ((1u << lane) - 1u))] = j * CC_N + cc;
            }
        }
    }
    __syncthreads();
    const int m = cnt;

    // gather: 4 warps stride the list, 8 uint2 LDGs in flight per warp
    float4 acc0 = make_float4(0.f, 0.f, 0.f, 0.f);
    float4 acc1 = make_float4(0.f, 0.f, 0.f, 0.f);
    const int co = lane * 4;

    #define ACCUM(A, u) do {                                              \
        const __half2 _h0 = *reinterpret_cast<const __half2*>(&(u).x);    \
        const __half2 _h1 = *reinterpret_cast<const __half2*>(&(u).y);    \
        const float2 _f0 = __half22float2(_h0);                           \
        const float2 _f1 = __half22float2(_h1);                           \
        A.x += _f0.x; A.y += _f0.y; A.z += _f1.x; A.w += _f1.y;           \
    } while (0)

    int e = w;
    for (; e + 28 < m; e += 32) {
        const int p0 = lst[e];      const int p1 = lst[e + 4];
        const int p2 = lst[e + 8];  const int p3 = lst[e + 12];
        const int p4 = lst[e + 16]; const int p5 = lst[e + 20];
        const int p6 = lst[e + 24]; const int p7 = lst[e + 28];
        const uint2 v0 = *reinterpret_cast<const uint2*>(g_Hh + (size_t)p0 * OUTD + co);
        const uint2 v1 = *reinterpret_cast<const uint2*>(g_Hh + (size_t)p1 * OUTD + co);
        const uint2 v2 = *reinterpret_cast<const uint2*>(g_Hh + (size_t)p2 * OUTD + co);
        const uint2 v3 = *reinterpret_cast<const uint2*>(g_Hh + (size_t)p3 * OUTD + co);
        const uint2 v4 = *reinterpret_cast<const uint2*>(g_Hh + (size_t)p4 * OUTD + co);
        const uint2 v5 = *reinterpret_cast<const uint2*>(g_Hh + (size_t)p5 * OUTD + co);
        const uint2 v6 = *reinterpret_cast<const uint2*>(g_Hh + (size_t)p6 * OUTD + co);
        const uint2 v7 = *reinterpret_cast<const uint2*>(g_Hh + (size_t)p7 * OUTD + co);
        ACCUM(acc0, v0); ACCUM(acc1, v1); ACCUM(acc0, v2); ACCUM(acc1, v3);
        ACCUM(acc0, v4); ACCUM(acc1, v5); ACCUM(acc0, v6); ACCUM(acc1, v7);
    }
    for (; e < m; e += 4) {
        const int p = lst[e];
        const uint2 v = *reinterpret_cast<const uint2*>(g_Hh + (size_t)p * OUTD + co);
        ACCUM(acc0, v);
    }
    #undef ACCUM
    acc0.x += acc1.x; acc0.y += acc1.y; acc0.z += acc1.z; acc0.w += acc1.w;

    *reinterpret_cast<float4*>(&red[w][co]) = acc0;
    __syncthreads();

    if (t < OUTD) {
        float s = bias[t];
        #pragma unroll
        for (int r = 0; r < 4; ++r) s += red[r][t];
        out[(size_t)i * OUTD + t] = fmaxf(s, 0.f);
    }
}

// ---------------------------------------------------------------------------
// inputs: hidden_state (n,128) f32 | obs1 (n,2) (unused) | obs2 (n,2) f32 |
//         W (2048,128) f32 | b (128,) f32   -> out (n,128) f32
// ---------------------------------------------------------------------------
extern "C" void kernel_launch(void* const* d_in, const int* in_sizes, int n_in,
                              void* d_out, int out_size)
{
    const float* hidden = (const float*)d_in[0];
    const float* obs2   = (const float*)d_in[2];
    const float* W      = (const float*)d_in[3];
    const float* bias   = (const float*)d_in[4];
    float*       out    = (float*)d_out;

    const int n = in_sizes[2] / 2;   // 512

    convert_kernel<<<320, 256>>>(hidden, W, n);
    dim3 g1((n + BM - 1) / BM, CC_N);
    gemm1_mma_kernel<<<g1, 256>>>(n);
    scatter_gather_kernel<<<n, 128>>>(obs2, bias, out, n);
}